// round 3
// baseline (speedup 1.0000x reference)
#include <cuda_runtime.h>
#include <cuda_bf16.h>
#include <math.h>

#define NMAX 200000
#define EPS 1e-15f

// Per-node accumulator {denom, pad, msum.x, msum.y}, 16B aligned for red.v4.
// Zero at module load (.bss); node_pass re-zeros after reading => invariant
// "zeroed before every kernel_launch" holds for all graph replays.
__device__ __align__(16) float4 g_accum[NMAX];

typedef unsigned long long u64;

// ---------- packed f32x2 helpers ----------
__device__ __forceinline__ u64 pk2(float lo, float hi) {
    u64 r; asm("mov.b64 %0,{%1,%2};" : "=l"(r) : "f"(lo), "f"(hi)); return r;
}
__device__ __forceinline__ void upk2(u64 v, float& a, float& b) {
    asm("mov.b64 {%0,%1},%2;" : "=f"(a), "=f"(b) : "l"(v));
}
__device__ __forceinline__ u64 ffma2(u64 a, u64 b, u64 c) {
    u64 d; asm("fma.rn.f32x2 %0,%1,%2,%3;" : "=l"(d) : "l"(a), "l"(b), "l"(c)); return d;
}
__device__ __forceinline__ u64 fmul2(u64 a, u64 b) {
    u64 d; asm("mul.rn.f32x2 %0,%1,%2;" : "=l"(d) : "l"(a), "l"(b)); return d;
}
__device__ __forceinline__ u64 fadd2(u64 a, u64 b) {
    u64 d; asm("add.rn.f32x2 %0,%1,%2;" : "=l"(d) : "l"(a), "l"(b)); return d;
}
// ---------- scalar MUFU helpers ----------
__device__ __forceinline__ float frcp(float x)  { float r; asm("rcp.approx.f32 %0,%1;"   : "=f"(r) : "f"(x)); return r; }
__device__ __forceinline__ float fex2(float x)  { float r; asm("ex2.approx.f32 %0,%1;"   : "=f"(r) : "f"(x)); return r; }
__device__ __forceinline__ float flg2(float x)  { float r; asm("lg2.approx.f32 %0,%1;"   : "=f"(r) : "f"(x)); return r; }
__device__ __forceinline__ float frsq(float x)  { float r; asm("rsqrt.approx.f32 %0,%1;" : "=f"(r) : "f"(x)); return r; }

#define SIGN2 0x8000000080000000ULL
#define ABS2  0x7FFFFFFF7FFFFFFFULL

// v = log_{xi}(xj) on the Poincare disk (c = 1)
__device__ __forceinline__ float2 compute_v(float2 xi, float2 xj) {
    float dot = xi.x * xj.x + xi.y * xj.y;
    float aa = xi.x * xi.x + xi.y * xi.y;
    float bb = xj.x * xj.x + xj.y * xj.y;
    float f1 = 1.0f - 2.0f * dot + bb;   // coeff of (-xi)   (ab_ref = -dot)
    float f2 = 1.0f - aa;                // coeff of xj; also = 2/lam_i
    float den = 1.0f - 2.0f * dot + aa * bb;
    float inv_den = frcp(fmaxf(den, EPS));
    float ux = (f1 * (-xi.x) + f2 * xj.x) * inv_den;
    float uy = (f1 * (-xi.y) + f2 * xj.y) * inv_den;
    float uu = ux * ux + uy * uy;
    float inv_un = frsq(fmaxf(uu, 1e-30f));
    float un = uu * inv_un;              // = |u|
    float t = fminf(un, 1.0f - 1e-5f);
    // atanh(t) = 0.5*ln((1+t)/(1-t)) = 0.34657359 * lg2((1+t)/(1-t))
    float ratio = (1.0f + t) * frcp(1.0f - t);
    float ath = 0.34657359027997264f * flg2(ratio);
    float s = f2 * ath * inv_un;
    return make_float2(s * ux, s * uy);
}

// Packed erf (Abramowitz-Stegun 7.1.26, |abs err| <= ~2e-7), both lanes.
__device__ __forceinline__ u64 erf2(u64 z2, u64 ONE2, u64 P2,
                                    u64 A1, u64 A2, u64 A3, u64 A4, u64 A5) {
    u64 az = z2 & ABS2;
    u64 sg = z2 & SIGN2;
    u64 q = ffma2(P2, az, ONE2);                 // 1 + p|z|
    float qa, qb; upk2(q, qa, qb);
    u64 t = pk2(frcp(qa), frcp(qb));
    u64 zz = fmul2(z2, z2);
    u64 w = fmul2(zz, pk2(-1.4426950408889634f, -1.4426950408889634f)); // -z^2*log2e
    float wa, wb; upk2(w, wa, wb);
    u64 e = pk2(fex2(wa), fex2(wb));             // exp(-z^2)
    u64 r = ffma2(A5, t, A4);
    r = ffma2(r, t, A3);
    r = ffma2(r, t, A2);
    r = ffma2(r, t, A1);
    r = fmul2(r, t);
    u64 erfabs = ffma2(r, e ^ SIGN2, ONE2);      // 1 - r*exp(-z^2)  (>= 0)
    return erfabs ^ sg;
}

struct MlpW {
    u64 wa[8], wb[8], wc[8], w2[8];
};

__device__ __forceinline__ float mlp_score(float2 v, const MlpW& W,
                                           u64 ONE2, u64 P2,
                                           u64 A1, u64 A2, u64 A3, u64 A4, u64 A5) {
    const u64 ISQ2 = pk2(0.7071067811865476f, 0.7071067811865476f);
    const u64 HALF2 = pk2(0.5f, 0.5f);
    u64 vx2 = pk2(v.x, v.x);
    u64 vy2 = pk2(v.y, v.y);
    u64 sacc = 0ULL;  // {0.0f, 0.0f}
#pragma unroll
    for (int p = 0; p < 8; p++) {
        u64 h2 = ffma2(vx2, W.wa[p], ffma2(vy2, W.wb[p], W.wc[p]));
        u64 z2 = fmul2(h2, ISQ2);
        u64 er = erf2(z2, ONE2, P2, A1, A2, A3, A4, A5);
        u64 hh = fmul2(h2, HALF2);
        u64 g2 = ffma2(hh, er, hh);              // 0.5h(1+erf)
        sacc = ffma2(g2, W.w2[p], sacc);
    }
    float sa, sb; upk2(sacc, sa, sb);
    return sa + sb;
}

__device__ __forceinline__ void do_edge(float2 xi, float2 xj, int r,
                                        const MlpW& W,
                                        u64 ONE2, u64 P2,
                                        u64 A1, u64 A2, u64 A3, u64 A4, u64 A5) {
    float2 v = compute_v(xi, xj);
    float score = mlp_score(v, W, ONE2, P2, A1, A2, A3, A4, A5);
    // unshifted softmax numerator (scores bounded well below exp overflow)
    float ex = fex2(score * 1.4426950408889634f);
    float vx = ex * v.x, vy = ex * v.y;
    asm volatile("red.global.v4.f32.add [%0], {%1, %2, %3, %4};"
                 :: "l"(&g_accum[r]), "f"(ex), "f"(0.0f), "f"(vx), "f"(vy)
                 : "memory");
}

template <bool PAIRED>
__global__ void __launch_bounds__(256) edge_pass(
        const float2* __restrict__ x,
        const int* __restrict__ row,
        const int* __restrict__ col,
        const float* __restrict__ W1,
        const float* __restrict__ b1,
        const float* __restrict__ W2, int E) {
    // Pack weights into registers once per thread (hidden units in pairs).
    MlpW W;
    const float2* W1a = (const float2*)W1;        // row 0: a_k
    const float2* W1b = (const float2*)(W1 + 16); // row 1: b_k
    const float2* B1 = (const float2*)b1;
    const float2* W2p = (const float2*)W2;
#pragma unroll
    for (int p = 0; p < 8; p++) {
        float2 a = __ldg(&W1a[p]); W.wa[p] = pk2(a.x, a.y);
        float2 b = __ldg(&W1b[p]); W.wb[p] = pk2(b.x, b.y);
        float2 c = __ldg(&B1[p]);  W.wc[p] = pk2(c.x, c.y);
        float2 w = __ldg(&W2p[p]); W.w2[p] = pk2(w.x, w.y);
    }
    const u64 ONE2 = pk2(1.0f, 1.0f);
    const u64 P2 = pk2(0.3275911f, 0.3275911f);
    const u64 A1 = pk2(0.254829592f, 0.254829592f);
    const u64 A2 = pk2(-0.284496736f, -0.284496736f);
    const u64 A3 = pk2(1.421413741f, 1.421413741f);
    const u64 A4 = pk2(-1.453152027f, -1.453152027f);
    const u64 A5 = pk2(1.061405429f, 1.061405429f);

    int npairs = (E + 1) >> 1;
    int stride = gridDim.x * blockDim.x;
    for (int p = blockIdx.x * blockDim.x + threadIdx.x; p < npairs; p += stride) {
        int e0 = 2 * p;
        if (PAIRED) {
            int2 rr = *(const int2*)(row + e0);
            int2 cc = *(const int2*)(col + e0);
            float2 xi0 = __ldg(&x[rr.x]);
            float2 xj0 = __ldg(&x[cc.x]);
            float2 xi1 = __ldg(&x[rr.y]);
            float2 xj1 = __ldg(&x[cc.y]);
            do_edge(xi0, xj0, rr.x, W, ONE2, P2, A1, A2, A3, A4, A5);
            do_edge(xi1, xj1, rr.y, W, ONE2, P2, A1, A2, A3, A4, A5);
        } else {
            int r0 = __ldg(&row[e0]);
            int c0 = __ldg(&col[e0]);
            do_edge(__ldg(&x[r0]), __ldg(&x[c0]), r0, W, ONE2, P2, A1, A2, A3, A4, A5);
            if (e0 + 1 < E) {
                int r1 = __ldg(&row[e0 + 1]);
                int c1 = __ldg(&col[e0 + 1]);
                do_edge(__ldg(&x[r1]), __ldg(&x[c1]), r1, W, ONE2, P2, A1, A2, A3, A4, A5);
            }
        }
    }
}

__global__ void __launch_bounds__(256) node_pass(
        const float2* __restrict__ x,
        const int* __restrict__ depth,
        const float* __restrict__ eta_p,
        const float* __restrict__ depth_scale,
        const float* __restrict__ depth_theta,
        float* __restrict__ out, int n) {
    int i = blockIdx.x * blockDim.x + threadIdx.x;
    if (i >= n) return;
    float eta = __ldg(eta_p);
    float2 xv = __ldg(&x[i]);
    float4 acc = g_accum[i];
    g_accum[i] = make_float4(0.0f, 0.0f, 0.0f, 0.0f);  // reset for next launch
    float inv_d = frcp(fmaxf(acc.x, 1e-15f));
    float mx = acc.z * inv_d, my = acc.w * inv_d;

    int d = min(max(depth[i], 0), 511);
    float k = __ldg(&depth_scale[d]);
    float ang = __ldg(&depth_theta[d]);
    float sa, ca;
    sincosf(ang, &sa, &ca);
    float rx = k * (ca * mx - sa * my);
    float ry = k * (sa * mx + ca * my);

    // exp_x(eta * m)
    float wx = eta * rx, wy = eta * ry;
    float ww = wx * wx + wy * wy;
    float inv_wn = frsq(fmaxf(ww, 1e-30f));
    float wn = fmaxf(ww * inv_wn, EPS);
    float aa = xv.x * xv.x + xv.y * xv.y;
    float lam = 2.0f * frcp(fmaxf(1.0f - aa, EPS));
    float th = tanhf(lam * wn * 0.5f);
    float scale = th * frcp(wn);
    float sxv = scale * wx;
    float syv = scale * wy;

    // mobius_add(x, second, 1)
    float ab = xv.x * sxv + xv.y * syv;
    float bb = sxv * sxv + syv * syv;
    float fa = 1.0f + 2.0f * ab + bb;
    float fb = 1.0f - aa;
    float den = 1.0f + 2.0f * ab + aa * bb;
    float inv = frcp(fmaxf(den, EPS));
    out[2 * i]     = (fa * xv.x + fb * sxv) * inv;
    out[2 * i + 1] = (fa * xv.y + fb * syv) * inv;
}

extern "C" void kernel_launch(void* const* d_in, const int* in_sizes, int n_in,
                              void* d_out, int out_size) {
    const float* x           = (const float*)d_in[0];   // [N,2]
    const int*   edge_index  = (const int*)d_in[1];     // [2,E]
    const int*   depth       = (const int*)d_in[2];     // [N]
    const float* W1          = (const float*)d_in[3];   // [2,16]
    const float* b1          = (const float*)d_in[4];   // [16]
    const float* W2          = (const float*)d_in[5];   // [16,1]
    const float* eta         = (const float*)d_in[6];   // scalar
    const float* depth_scale = (const float*)d_in[7];   // [512,1]
    const float* depth_theta = (const float*)d_in[8];   // [512,1]
    float* out = (float*)d_out;

    int N = in_sizes[0] / 2;
    int E = in_sizes[1] / 2;
    const int* row = edge_index;
    const int* col = edge_index + E;
    const float2* x2 = (const float2*)x;

    int tb = 256;
    int npairs = (E + 1) / 2;
    int blocks = (npairs + tb * 4 - 1) / (tb * 4);  // ~4 pairs (8 edges) per thread
    if ((E & 1) == 0)
        edge_pass<true><<<blocks, tb>>>(x2, row, col, W1, b1, W2, E);
    else
        edge_pass<false><<<blocks, tb>>>(x2, row, col, W1, b1, W2, E);
    node_pass<<<(N + tb - 1) / tb, tb>>>(x2, depth, eta, depth_scale, depth_theta, out, N);
}